// round 8
// baseline (speedup 1.0000x reference)
#include <cuda_runtime.h>
#include <cstdint>

#define WDIM 1024
#define NPIX (WDIM * WDIM)
#define HALF (NPIX / 2)

// ---- constant-bank weights (written by prep kernel; read via the dedicated LDC port) ----
// CW1[(c*9+j)*8 + k] : 16B = w1t[cj][4k..4k+3]  (w1t[cj][o] = w1[o][cj])
// CW2[o*4 + i]       : 16B = w2t[o][4i..4i+3]   (w2t[o][m] = w2[m][o], m>=13 -> 0)
__constant__ __align__(16) ulonglong2 CW1[54 * 8];
__constant__ __align__(16) ulonglong2 CW2[32 * 4];
__constant__ __align__(16) unsigned long long CB1[16];
__constant__ __align__(16) unsigned long long CB2[7];

static __device__ __forceinline__ unsigned long long pack2(float a, float b) {
    unsigned long long r;
    asm("mov.b64 %0, {%1,%2};" : "=l"(r) : "f"(a), "f"(b));
    return r;
}
static __device__ __forceinline__ void fma2(unsigned long long& d, unsigned long long a, unsigned long long b) {
    asm("fma.rn.f32x2 %0, %1, %2, %0;" : "+l"(d) : "l"(a), "l"(b));
}
static __device__ __forceinline__ float2 unpack2(unsigned long long v) {
    float2 r;
    asm("mov.b64 {%0,%1}, %2;" : "=f"(r.x), "=f"(r.y) : "l"(v));
    return r;
}

// Prep: transpose/pack weights into the constant bank via its global alias.
__global__ void prep_kernel(const float* __restrict__ w1, const float* __restrict__ b1,
                            const float* __restrict__ w2, const float* __restrict__ b2,
                            float* __restrict__ cw1, float* __restrict__ cw2,
                            float* __restrict__ cb1, float* __restrict__ cb2)
{
    const int tid = threadIdx.x;
    for (int i = tid; i < 54 * 32; i += 256) {
        int cj = i >> 5, o = i & 31;
        cw1[i] = w1[o * 54 + cj];
    }
    for (int i = tid; i < 32 * 16; i += 256) {
        int o = i >> 4, m = i & 15;
        cw2[i] = (m < 13) ? w2[m * 32 + o] : 0.0f;
    }
    if (tid < 32) cb1[tid] = b1[tid];
    if (tid < 14) cb2[tid] = (tid < 13) ? b2[tid] : 0.0f;
}

// softmax(9) + inverse rotation (register selects) + tanh + sigmoid; coalesced stores.
static __device__ __forceinline__ void epilogue(const float* z, int d, int p,
                                                float* __restrict__ out)
{
    const int rb0 = d & 1;
    const int rb1 = (d >> 1) & 1;

    float mx = z[0];
#pragma unroll
    for (int j = 1; j < 9; j++) mx = fmaxf(mx, z[j]);
    float s[9];
    float sum = 0.0f;
#pragma unroll
    for (int j = 0; j < 9; j++) { s[j] = __expf(z[j] - mx); sum += s[j]; }
    float inv = __fdividef(1.0f, sum);

    const int I0[9] = {0,1,2,3,4,5,6,7,8};
    const int I1[9] = {2,5,8,1,4,7,0,3,6};
    const int I2[9] = {8,7,6,5,4,3,2,1,0};
    const int I3[9] = {6,3,0,7,4,1,8,5,2};
#pragma unroll
    for (int m = 0; m < 9; m++) {
        float v01 = rb0 ? s[I1[m]] : s[I0[m]];
        float v23 = rb0 ? s[I3[m]] : s[I2[m]];
        float v = rb1 ? v23 : v01;
        out[m * NPIX + p] = v * inv;
    }
    out[9 * NPIX + p] = tanhf(z[9]);
#pragma unroll
    for (int m = 0; m < 3; m++)
        out[(10 + m) * NPIX + p] = __fdividef(1.0f, 1.0f + __expf(-z[10 + m]));
}

__global__ void __launch_bounds__(128, 5) energy_cnn_kernel(
    const float* __restrict__ se, const float* __restrict__ te,
    const float* __restrict__ sr, const float* __restrict__ hc,
    const float* __restrict__ rot, float* __restrict__ out)
{
    const int tid = threadIdx.x;

    // Two pixels per thread: p0 top half, p1 = p0 + HALF.
    const int p0 = blockIdx.x * 128 + tid;
    const int p1 = p0 + HALF;
    const int x0 = p0 & (WDIM - 1), y0 = p0 >> 10;
    const int x1 = x0,              y1 = y0 + (WDIM / 2);

    const float TP = 6.2831853071795864f;
    int d0, d1;
    {
        float t = rot[p0] / TP * 4.0f;  d0 = ((int)t) & 3;
        float u = rot[p1] / TP * 4.0f;  d1 = ((int)u) & 3;
    }

    // Rotated gather addresses (rotation = address permutation).
    int idx0[9], idx1[9];
    {
        const int rb00 = d0 & 1, rb01 = (d0 >> 1) & 1;
        const int rb10 = d1 & 1, rb11 = (d1 >> 1) & 1;
#pragma unroll
        for (int j = 0; j < 9; j++) {
            const int dy0 = j / 3 - 1, dx0 = j % 3 - 1;
            {
                int ay = rb01 ? -dy0 : dy0;
                int ax = rb01 ? -dx0 : dx0;
                int dy = rb00 ? -ax : ay;
                int dx = rb00 ? ay : ax;
                idx0[j] = (((y0 + dy) & (WDIM - 1)) << 10) + ((x0 + dx) & (WDIM - 1));
            }
            {
                int ay = rb11 ? -dy0 : dy0;
                int ax = rb11 ? -dx0 : dx0;
                int dy = rb10 ? -ax : ay;
                int dx = rb10 ? ay : ax;
                idx1[j] = (((y1 + dy) & (WDIM - 1)) << 10) + ((x1 + dx) & (WDIM - 1));
            }
        }
    }

    const float* chans[6] = { se, te, sr, hc, hc + NPIX, hc + 2 * NPIX };

    // Persistent layer-2 accumulators (13 outputs = 7 pairs, per pixel).
    unsigned long long x20[7], x21[7];
#pragma unroll
    for (int m = 0; m < 7; m++) {
        unsigned long long b = CB2[m];
        x20[m] = b; x21[m] = b;
    }

    // Process the 32 hidden channels in two halves of 16 to halve the live
    // accumulator registers; fuse each half's layer-2 partial right after ReLU.
#pragma unroll
    for (int half = 0; half < 2; half++) {
        // ---- layer 1 (this half): 54 -> 16 ----
        unsigned long long acc0[8], acc1[8];
#pragma unroll
        for (int i = 0; i < 8; i++) {
            unsigned long long b = CB1[half * 8 + i];
            acc0[i] = b; acc1[i] = b;
        }

#pragma unroll
        for (int c = 0; c < 6; c++) {
            const float* __restrict__ ch = chans[c];
#pragma unroll
            for (int j = 0; j < 9; j++) {
                float a0 = __ldg(&ch[idx0[j]]);
                float a1 = __ldg(&ch[idx1[j]]);
                unsigned long long aa0 = pack2(a0, a0);
                unsigned long long aa1 = pack2(a1, a1);
#pragma unroll
                for (int k = 0; k < 4; k++) {
                    ulonglong2 wv = CW1[(c * 9 + j) * 8 + half * 4 + k];  // LDC.128
                    fma2(acc0[2 * k],     aa0, wv.x);
                    fma2(acc0[2 * k + 1], aa0, wv.y);
                    fma2(acc1[2 * k],     aa1, wv.x);
                    fma2(acc1[2 * k + 1], aa1, wv.y);
                }
            }
        }

        // ReLU for this half's 16 channels.
        float h0[16], h1[16];
#pragma unroll
        for (int i = 0; i < 8; i++) {
            float2 v0 = unpack2(acc0[i]);
            float2 v1 = unpack2(acc1[i]);
            h0[2 * i]     = fmaxf(v0.x, 0.0f);
            h0[2 * i + 1] = fmaxf(v0.y, 0.0f);
            h1[2 * i]     = fmaxf(v1.x, 0.0f);
            h1[2 * i + 1] = fmaxf(v1.y, 0.0f);
        }

        // ---- layer-2 partial for this half's 16 input channels ----
#pragma unroll
        for (int oo = 0; oo < 16; oo++) {
            const int o = half * 16 + oo;
            unsigned long long hh0 = pack2(h0[oo], h0[oo]);
            unsigned long long hh1 = pack2(h1[oo], h1[oo]);
            ulonglong2 wv0 = CW2[o * 4 + 0];
            ulonglong2 wv1 = CW2[o * 4 + 1];
            ulonglong2 wv2 = CW2[o * 4 + 2];
            ulonglong2 wv3 = CW2[o * 4 + 3];
            fma2(x20[0], hh0, wv0.x);  fma2(x21[0], hh1, wv0.x);
            fma2(x20[1], hh0, wv0.y);  fma2(x21[1], hh1, wv0.y);
            fma2(x20[2], hh0, wv1.x);  fma2(x21[2], hh1, wv1.x);
            fma2(x20[3], hh0, wv1.y);  fma2(x21[3], hh1, wv1.y);
            fma2(x20[4], hh0, wv2.x);  fma2(x21[4], hh1, wv2.x);
            fma2(x20[5], hh0, wv2.y);  fma2(x21[5], hh1, wv2.y);
            fma2(x20[6], hh0, wv3.x);  fma2(x21[6], hh1, wv3.x);
        }
    }

    float z0[13], z1[13];
#pragma unroll
    for (int m = 0; m < 6; m++) {
        float2 v0 = unpack2(x20[m]);
        float2 v1 = unpack2(x21[m]);
        z0[2 * m] = v0.x; z0[2 * m + 1] = v0.y;
        z1[2 * m] = v1.x; z1[2 * m + 1] = v1.y;
    }
    z0[12] = unpack2(x20[6]).x;
    z1[12] = unpack2(x21[6]).x;

    epilogue(z0, d0, p0, out);
    epilogue(z1, d1, p1, out);
}

extern "C" void kernel_launch(void* const* d_in, const int* in_sizes, int n_in,
                              void* d_out, int out_size)
{
    const float* se  = (const float*)d_in[0];
    const float* te  = (const float*)d_in[1];
    const float* sr  = (const float*)d_in[2];
    const float* hc  = (const float*)d_in[3];
    const float* rot = (const float*)d_in[4];
    const float* w1  = (const float*)d_in[5];
    const float* b1  = (const float*)d_in[6];
    const float* w2  = (const float*)d_in[7];
    const float* b2  = (const float*)d_in[8];
    float* out = (float*)d_out;

    void *cw1p, *cw2p, *cb1p, *cb2p;
    cudaGetSymbolAddress(&cw1p, CW1);
    cudaGetSymbolAddress(&cw2p, CW2);
    cudaGetSymbolAddress(&cb1p, CB1);
    cudaGetSymbolAddress(&cb2p, CB2);

    prep_kernel<<<1, 256>>>(w1, b1, w2, b2,
                            (float*)cw1p, (float*)cw2p, (float*)cb1p, (float*)cb2p);
    energy_cnn_kernel<<<HALF / 128, 128>>>(se, te, sr, hc, rot, out);
}

// round 9
// speedup vs baseline: 1.6837x; 1.6837x over previous
#include <cuda_runtime.h>
#include <cstdint>

#define WDIM 1024
#define NPIX (WDIM * WDIM)
#define HALF (NPIX / 2)

// ---- constant-bank weights (written by prep kernel; read via the dedicated LDC port) ----
// CW1[(c*9+j)*8 + k] : 16B = w1t[cj][4k..4k+3]  (w1t[cj][o] = w1[o][cj])
// CW2[o*4 + i]       : 16B = w2t[o][4i..4i+3]   (w2t[o][m] = w2[m][o], m>=13 -> 0)
__constant__ __align__(16) ulonglong2 CW1[54 * 8];
__constant__ __align__(16) ulonglong2 CW2[32 * 4];
__constant__ __align__(16) unsigned long long CB1[16];
__constant__ __align__(16) unsigned long long CB2[7];

static __device__ __forceinline__ unsigned long long pack2(float a, float b) {
    unsigned long long r;
    asm("mov.b64 %0, {%1,%2};" : "=l"(r) : "f"(a), "f"(b));
    return r;
}
static __device__ __forceinline__ void fma2(unsigned long long& d, unsigned long long a, unsigned long long b) {
    asm("fma.rn.f32x2 %0, %1, %2, %0;" : "+l"(d) : "l"(a), "l"(b));
}
static __device__ __forceinline__ float2 unpack2(unsigned long long v) {
    float2 r;
    asm("mov.b64 {%0,%1}, %2;" : "=f"(r.x), "=f"(r.y) : "l"(v));
    return r;
}

// Prep: transpose/pack weights into the constant bank via its global alias.
__global__ void prep_kernel(const float* __restrict__ w1, const float* __restrict__ b1,
                            const float* __restrict__ w2, const float* __restrict__ b2,
                            float* __restrict__ cw1, float* __restrict__ cw2,
                            float* __restrict__ cb1, float* __restrict__ cb2)
{
    const int tid = threadIdx.x;
    for (int i = tid; i < 54 * 32; i += 256) {
        int cj = i >> 5, o = i & 31;
        cw1[i] = w1[o * 54 + cj];
    }
    for (int i = tid; i < 32 * 16; i += 256) {
        int o = i >> 4, m = i & 15;
        cw2[i] = (m < 13) ? w2[m * 32 + o] : 0.0f;
    }
    if (tid < 32) cb1[tid] = b1[tid];
    if (tid < 14) cb2[tid] = (tid < 13) ? b2[tid] : 0.0f;
}

// softmax(9) + inverse rotation (register selects) + tanh + sigmoid; coalesced stores.
static __device__ __forceinline__ void epilogue(const float* z, int d, int p,
                                                float* __restrict__ out)
{
    const int rb0 = d & 1;
    const int rb1 = (d >> 1) & 1;

    float mx = z[0];
#pragma unroll
    for (int j = 1; j < 9; j++) mx = fmaxf(mx, z[j]);
    float s[9];
    float sum = 0.0f;
#pragma unroll
    for (int j = 0; j < 9; j++) { s[j] = __expf(z[j] - mx); sum += s[j]; }
    float inv = __fdividef(1.0f, sum);

    const int I0[9] = {0,1,2,3,4,5,6,7,8};
    const int I1[9] = {2,5,8,1,4,7,0,3,6};
    const int I2[9] = {8,7,6,5,4,3,2,1,0};
    const int I3[9] = {6,3,0,7,4,1,8,5,2};
#pragma unroll
    for (int m = 0; m < 9; m++) {
        float v01 = rb0 ? s[I1[m]] : s[I0[m]];
        float v23 = rb0 ? s[I3[m]] : s[I2[m]];
        float v = rb1 ? v23 : v01;
        out[m * NPIX + p] = v * inv;
    }
    out[9 * NPIX + p] = tanhf(z[9]);
#pragma unroll
    for (int m = 0; m < 3; m++)
        out[(10 + m) * NPIX + p] = __fdividef(1.0f, 1.0f + __expf(-z[10 + m]));
}

__global__ void __launch_bounds__(128, 5) energy_cnn_kernel(
    const float* __restrict__ se, const float* __restrict__ te,
    const float* __restrict__ sr, const float* __restrict__ hc,
    const float* __restrict__ rot, float* __restrict__ out)
{
    const int tid = threadIdx.x;

    // Two pixels per thread: p0 top half, p1 = p0 + HALF.
    const int p0 = blockIdx.x * 128 + tid;
    const int p1 = p0 + HALF;
    const int x0 = p0 & (WDIM - 1), y0 = p0 >> 10;
    const int x1 = x0,              y1 = y0 + (WDIM / 2);

    const float TP = 6.2831853071795864f;
    int d0, d1;
    {
        float t = rot[p0] / TP * 4.0f;  d0 = ((int)t) & 3;
        float u = rot[p1] / TP * 4.0f;  d1 = ((int)u) & 3;
    }

    // Rotated gather addresses (rotation = address permutation).
    int idx0[9], idx1[9];
    {
        const int rb00 = d0 & 1, rb01 = (d0 >> 1) & 1;
        const int rb10 = d1 & 1, rb11 = (d1 >> 1) & 1;
#pragma unroll
        for (int j = 0; j < 9; j++) {
            const int dy0 = j / 3 - 1, dx0 = j % 3 - 1;
            {
                int ay = rb01 ? -dy0 : dy0;
                int ax = rb01 ? -dx0 : dx0;
                int dy = rb00 ? -ax : ay;
                int dx = rb00 ? ay : ax;
                idx0[j] = (((y0 + dy) & (WDIM - 1)) << 10) + ((x0 + dx) & (WDIM - 1));
            }
            {
                int ay = rb11 ? -dy0 : dy0;
                int ax = rb11 ? -dx0 : dx0;
                int dy = rb10 ? -ax : ay;
                int dx = rb10 ? ay : ax;
                idx1[j] = (((y1 + dy) & (WDIM - 1)) << 10) + ((x1 + dx) & (WDIM - 1));
            }
        }
    }

    // ---- layer 1: 54 -> 32, single pass, ALL gathers issued exactly once ----
    unsigned long long acc0[16], acc1[16];
#pragma unroll
    for (int i = 0; i < 16; i++) {
        unsigned long long b = CB1[i];
        acc0[i] = b; acc1[i] = b;
    }

    const float* chans[6] = { se, te, sr, hc, hc + NPIX, hc + 2 * NPIX };
#pragma unroll
    for (int c = 0; c < 6; c++) {
        const float* __restrict__ ch = chans[c];
#pragma unroll
        for (int j = 0; j < 9; j++) {
            float a0 = __ldg(&ch[idx0[j]]);
            float a1 = __ldg(&ch[idx1[j]]);
            unsigned long long aa0 = pack2(a0, a0);
            unsigned long long aa1 = pack2(a1, a1);
#pragma unroll
            for (int k = 0; k < 8; k++) {
                ulonglong2 wv = CW1[(c * 9 + j) * 8 + k];   // LDC.128 (constant port)
                fma2(acc0[2 * k],     aa0, wv.x);
                fma2(acc0[2 * k + 1], aa0, wv.y);
                fma2(acc1[2 * k],     aa1, wv.x);
                fma2(acc1[2 * k + 1], aa1, wv.y);
            }
        }
    }

    // ---- fused ReLU + layer 2: consume each accumulator pair immediately ----
    // (no h[] array: peak live registers = x2(28) + remaining acc)
    unsigned long long x20[7], x21[7];
#pragma unroll
    for (int m = 0; m < 7; m++) {
        unsigned long long b = CB2[m];
        x20[m] = b; x21[m] = b;
    }

#pragma unroll
    for (int i = 0; i < 16; i++) {
        float2 v0 = unpack2(acc0[i]);
        float2 v1 = unpack2(acc1[i]);
        float ha0 = fmaxf(v0.x, 0.0f), hb0 = fmaxf(v0.y, 0.0f);
        float ha1 = fmaxf(v1.x, 0.0f), hb1 = fmaxf(v1.y, 0.0f);

        // channel o = 2i
        {
            unsigned long long hh0 = pack2(ha0, ha0);
            unsigned long long hh1 = pack2(ha1, ha1);
            ulonglong2 wv0 = CW2[(2 * i) * 4 + 0];
            ulonglong2 wv1 = CW2[(2 * i) * 4 + 1];
            ulonglong2 wv2 = CW2[(2 * i) * 4 + 2];
            ulonglong2 wv3 = CW2[(2 * i) * 4 + 3];
            fma2(x20[0], hh0, wv0.x);  fma2(x21[0], hh1, wv0.x);
            fma2(x20[1], hh0, wv0.y);  fma2(x21[1], hh1, wv0.y);
            fma2(x20[2], hh0, wv1.x);  fma2(x21[2], hh1, wv1.x);
            fma2(x20[3], hh0, wv1.y);  fma2(x21[3], hh1, wv1.y);
            fma2(x20[4], hh0, wv2.x);  fma2(x21[4], hh1, wv2.x);
            fma2(x20[5], hh0, wv2.y);  fma2(x21[5], hh1, wv2.y);
            fma2(x20[6], hh0, wv3.x);  fma2(x21[6], hh1, wv3.x);
        }
        // channel o = 2i+1
        {
            unsigned long long hh0 = pack2(hb0, hb0);
            unsigned long long hh1 = pack2(hb1, hb1);
            ulonglong2 wv0 = CW2[(2 * i + 1) * 4 + 0];
            ulonglong2 wv1 = CW2[(2 * i + 1) * 4 + 1];
            ulonglong2 wv2 = CW2[(2 * i + 1) * 4 + 2];
            ulonglong2 wv3 = CW2[(2 * i + 1) * 4 + 3];
            fma2(x20[0], hh0, wv0.x);  fma2(x21[0], hh1, wv0.x);
            fma2(x20[1], hh0, wv0.y);  fma2(x21[1], hh1, wv0.y);
            fma2(x20[2], hh0, wv1.x);  fma2(x21[2], hh1, wv1.x);
            fma2(x20[3], hh0, wv1.y);  fma2(x21[3], hh1, wv1.y);
            fma2(x20[4], hh0, wv2.x);  fma2(x21[4], hh1, wv2.x);
            fma2(x20[5], hh0, wv2.y);  fma2(x21[5], hh1, wv2.y);
            fma2(x20[6], hh0, wv3.x);  fma2(x21[6], hh1, wv3.x);
        }
    }

    float z0[13], z1[13];
#pragma unroll
    for (int m = 0; m < 6; m++) {
        float2 v0 = unpack2(x20[m]);
        float2 v1 = unpack2(x21[m]);
        z0[2 * m] = v0.x; z0[2 * m + 1] = v0.y;
        z1[2 * m] = v1.x; z1[2 * m + 1] = v1.y;
    }
    z0[12] = unpack2(x20[6]).x;
    z1[12] = unpack2(x21[6]).x;

    epilogue(z0, d0, p0, out);
    epilogue(z1, d1, p1, out);
}

extern "C" void kernel_launch(void* const* d_in, const int* in_sizes, int n_in,
                              void* d_out, int out_size)
{
    const float* se  = (const float*)d_in[0];
    const float* te  = (const float*)d_in[1];
    const float* sr  = (const float*)d_in[2];
    const float* hc  = (const float*)d_in[3];
    const float* rot = (const float*)d_in[4];
    const float* w1  = (const float*)d_in[5];
    const float* b1  = (const float*)d_in[6];
    const float* w2  = (const float*)d_in[7];
    const float* b2  = (const float*)d_in[8];
    float* out = (float*)d_out;

    void *cw1p, *cw2p, *cb1p, *cb2p;
    cudaGetSymbolAddress(&cw1p, CW1);
    cudaGetSymbolAddress(&cw2p, CW2);
    cudaGetSymbolAddress(&cb1p, CB1);
    cudaGetSymbolAddress(&cb2p, CB2);

    prep_kernel<<<1, 256>>>(w1, b1, w2, b2,
                            (float*)cw1p, (float*)cw2p, (float*)cb1p, (float*)cb2p);
    energy_cnn_kernel<<<HALF / 128, 128>>>(se, te, sr, hc, rot, out);
}

// round 11
// speedup vs baseline: 2.1272x; 1.2634x over previous
#include <cuda_runtime.h>
#include <cuda_bf16.h>
#include <cstdint>

#define WDIM 1024
#define NPIX (WDIM * WDIM)
#define TPC 4
#define NCTA (NPIX / 128 / TPC)   // 2048

static __device__ __forceinline__ float bt(float v) {
    return __bfloat162float(__float2bfloat16_rn(v));
}
static __device__ __forceinline__ uint32_t pk(float lo, float hi) {
    uint32_t r;
    asm("cvt.rn.bf16x2.f32 %0, %1, %2;" : "=r"(r) : "f"(hi), "f"(lo));
    return r;
}
static __device__ __forceinline__ uint32_t smem_u32(const void* p) {
    uint32_t a;
    asm("{ .reg .u64 t; cvta.to.shared.u64 t, %1; cvt.u32.u64 %0, t; }" : "=r"(a) : "l"(p));
    return a;
}
static __device__ __forceinline__ void mma16816(float* d, const uint32_t* a,
                                                uint32_t b0, uint32_t b1) {
    asm volatile(
        "mma.sync.aligned.m16n8k16.row.col.f32.bf16.bf16.f32 "
        "{%0,%1,%2,%3}, {%4,%5,%6,%7}, {%8,%9}, {%0,%1,%2,%3};"
        : "+f"(d[0]), "+f"(d[1]), "+f"(d[2]), "+f"(d[3])
        : "r"(a[0]), "r"(a[1]), "r"(a[2]), "r"(a[3]), "r"(b0), "r"(b1));
}
static __device__ __forceinline__ void ldm4(uint32_t* r, uint32_t addr) {
    asm volatile("ldmatrix.sync.aligned.m8n8.x4.shared.b16 {%0,%1,%2,%3}, [%4];"
                 : "=r"(r[0]), "=r"(r[1]), "=r"(r[2]), "=r"(r[3]) : "r"(addr));
}

// softmax(9) + inverse rotation (register selects) + tanh + sigmoid; coalesced stores.
static __device__ __forceinline__ void epilogue(const float* z, int d, int p,
                                                float* __restrict__ out)
{
    const int rb0 = d & 1;
    const int rb1 = (d >> 1) & 1;

    float mx = z[0];
#pragma unroll
    for (int j = 1; j < 9; j++) mx = fmaxf(mx, z[j]);
    float s[9];
    float sum = 0.0f;
#pragma unroll
    for (int j = 0; j < 9; j++) { s[j] = __expf(z[j] - mx); sum += s[j]; }
    float inv = __fdividef(1.0f, sum);

    const int I0[9] = {0,1,2,3,4,5,6,7,8};
    const int I1[9] = {2,5,8,1,4,7,0,3,6};
    const int I2[9] = {8,7,6,5,4,3,2,1,0};
    const int I3[9] = {6,3,0,7,4,1,8,5,2};
#pragma unroll
    for (int m = 0; m < 9; m++) {
        float v01 = rb0 ? s[I1[m]] : s[I0[m]];
        float v23 = rb0 ? s[I3[m]] : s[I2[m]];
        float v = rb1 ? v23 : v01;
        out[m * NPIX + p] = v * inv;
    }
    out[9 * NPIX + p] = tanhf(z[9]);
#pragma unroll
    for (int m = 0; m < 3; m++)
        out[(10 + m) * NPIX + p] = __fdividef(1.0f, 1.0f + __expf(-z[10 + m]));
}

__global__ void __launch_bounds__(128, 4) energy_cnn_hmma_kernel(
    const float* __restrict__ se, const float* __restrict__ te,
    const float* __restrict__ sr, const float* __restrict__ hc,
    const float* __restrict__ rot, const float* __restrict__ w1,
    const float* __restrict__ b1, const float* __restrict__ w2,
    const float* __restrict__ b2, float* __restrict__ out)
{
    // A tiles: 128 rows x 64 bf16 (128B rows), XOR-16B-chunk swizzle.
    __shared__ __align__(128) uint8_t Ahi[128 * 128];
    __shared__ __align__(128) uint8_t Alo[128 * 128];
    // B fragment banks [frag][lane] (warp-uniform values, lane-private slots).
    __shared__ __align__(16) uint2 W1LO[16 * 32];
    __shared__ __align__(16) uint2 W2H[4 * 32];
    __shared__ __align__(16) uint2 W2L[4 * 32];
    // z staging, pitch 17 floats (conflict-free column reads).
    __shared__ float ZS[128 * 17];

    const int tid = threadIdx.x;
    const int lane = tid & 31, wid = tid >> 5;
    const int q = lane & 3, nrow = lane >> 2;

    // ---- build B fragments: w1-hi in registers (all warps), lo/w2 banks (warp 0) ----
    uint32_t w1h[4][4][2];
#pragma unroll
    for (int kt = 0; kt < 4; kt++)
#pragma unroll
    for (int nt = 0; nt < 4; nt++) {
        const int n = nt * 8 + nrow;
        const int k0 = kt * 16 + q * 2;
        float v[4];
#pragma unroll
        for (int u = 0; u < 4; u++) {
            int k = k0 + (u >> 1) * 8 + (u & 1);
            v[u] = (k < 54) ? __ldg(&w1[n * 54 + k]) : ((k == 54) ? __ldg(&b1[n]) : 0.0f);
        }
        float h0 = bt(v[0]), h1 = bt(v[1]), h2 = bt(v[2]), h3 = bt(v[3]);
        w1h[kt][nt][0] = pk(h0, h1);
        w1h[kt][nt][1] = pk(h2, h3);
        if (wid == 0)
            W1LO[(kt * 4 + nt) * 32 + lane] =
                make_uint2(pk(v[0] - h0, v[1] - h1), pk(v[2] - h2, v[3] - h3));
    }
    if (wid == 0) {
#pragma unroll
        for (int kt = 0; kt < 2; kt++)
#pragma unroll
        for (int nt = 0; nt < 2; nt++) {
            const int n = nt * 8 + nrow;
            const int k0 = kt * 16 + q * 2;
            float v[4];
#pragma unroll
            for (int u = 0; u < 4; u++) {
                int k = k0 + (u >> 1) * 8 + (u & 1);
                v[u] = (n < 13) ? __ldg(&w2[n * 32 + k]) : 0.0f;
            }
            float h0 = bt(v[0]), h1 = bt(v[1]), h2 = bt(v[2]), h3 = bt(v[3]);
            W2H[(kt * 2 + nt) * 32 + lane] = make_uint2(pk(h0, h1), pk(h2, h3));
            W2L[(kt * 2 + nt) * 32 + lane] =
                make_uint2(pk(v[0] - h0, v[1] - h1), pk(v[2] - h2, v[3] - h3));
        }
    }
    __syncthreads();

    const uint32_t sAhi = smem_u32(Ahi), sAlo = smem_u32(Alo);
    const float* chans[6] = { se, te, sr, hc, hc + NPIX, hc + 2 * NPIX };
    const float TP = 6.2831853071795864f;

    for (int t = 0; t < TPC; t++) {
        const int p = (blockIdx.x * TPC + t) * 128 + tid;
        const int x = p & (WDIM - 1);
        const int y = p >> 10;

        float tt = __ldg(&rot[p]) / TP * 4.0f;
        const int dd = ((int)tt) & 3;
        const int rb0 = dd & 1, rb1 = (dd >> 1) & 1;

        int idx[9];
#pragma unroll
        for (int j = 0; j < 9; j++) {
            const int dy0 = j / 3 - 1, dx0 = j % 3 - 1;
            int ay = rb1 ? -dy0 : dy0;
            int ax = rb1 ? -dx0 : dx0;
            int dy = rb0 ? -ax : ay;
            int dx = rb0 ? ay : ax;
            idx[j] = (((y + dy) & (WDIM - 1)) << 10) + ((x + dx) & (WDIM - 1));
        }

        // ---- gather + bf16 hi/lo pack + swizzled A-tile stores (row = tid) ----
        const int rx = tid & 7;
        const uint32_t rowo = (uint32_t)tid * 128u;
#pragma unroll
        for (int j = 0; j < 8; j++) {
            uint32_t wh[4], wl[4];
#pragma unroll
            for (int wi = 0; wi < 4; wi++) {
                const int w = j * 4 + wi;
                if (w < 27) {
                    const int e0 = 2 * w, e1 = 2 * w + 1;
                    float a0 = __ldg(&chans[e0 / 9][idx[e0 % 9]]);
                    float a1 = __ldg(&chans[e1 / 9][idx[e1 % 9]]);
                    float c0 = bt(a0), c1 = bt(a1);
                    wh[wi] = pk(c0, c1);
                    wl[wi] = pk(a0 - c0, a1 - c1);
                } else if (w == 27) {
                    wh[wi] = pk(1.0f, 0.0f);   // bias channel K=54 (exact), K=55 pad
                    wl[wi] = 0u;
                } else { wh[wi] = 0u; wl[wi] = 0u; }
            }
            const uint32_t off = rowo + ((uint32_t)(j ^ rx) << 4);
            *(uint4*)(Ahi + off) = make_uint4(wh[0], wh[1], wh[2], wh[3]);
            *(uint4*)(Alo + off) = make_uint4(wl[0], wl[1], wl[2], wl[3]);
        }
        __syncwarp();

        // ---- per-warp MMA over its 32 rows (two 16-row subtiles) ----
#pragma unroll
        for (int smt = 0; smt < 2; smt++) {
            const int rl = wid * 32 + smt * 16 + (lane & 15);
            const uint32_t rbase = (uint32_t)rl * 128u;
            const int rrx = rl & 7;
            const int sel = lane >> 4;

            uint32_t af[4][4];
#pragma unroll
            for (int kt = 0; kt < 4; kt++)
                ldm4(af[kt], sAhi + rbase + ((uint32_t)((kt * 2 + sel) ^ rrx) << 4));

            float d1[4][4];
#pragma unroll
            for (int nt = 0; nt < 4; nt++)
#pragma unroll
                for (int u = 0; u < 4; u++) d1[nt][u] = 0.0f;

#pragma unroll
            for (int nt = 0; nt < 4; nt++)
#pragma unroll
            for (int kt = 0; kt < 4; kt++) {
                mma16816(d1[nt], af[kt], w1h[kt][nt][0], w1h[kt][nt][1]);   // Ah*Wh
                uint2 fb = W1LO[(kt * 4 + nt) * 32 + lane];
                mma16816(d1[nt], af[kt], fb.x, fb.y);                       // Ah*Wl
            }
#pragma unroll
            for (int kt = 0; kt < 4; kt++)
                ldm4(af[kt], sAlo + rbase + ((uint32_t)((kt * 2 + sel) ^ rrx) << 4));
#pragma unroll
            for (int nt = 0; nt < 4; nt++)
#pragma unroll
            for (int kt = 0; kt < 4; kt++)
                mma16816(d1[nt], af[kt], w1h[kt][nt][0], w1h[kt][nt][1]);   // Al*Wh

            // ---- ReLU + hi/lo split -> layer-2 A fragments, register-resident ----
            uint32_t a2h[2][4], a2l[2][4];
#pragma unroll
            for (int kt2 = 0; kt2 < 2; kt2++) {
#pragma unroll
                for (int hh = 0; hh < 2; hh++) {     // D1 n-tile = 2*kt2 + hh
                    float* e = d1[2 * kt2 + hh];
                    float r0 = fmaxf(e[0], 0.0f), r1 = fmaxf(e[1], 0.0f);
                    float r2 = fmaxf(e[2], 0.0f), r3 = fmaxf(e[3], 0.0f);
                    float t0 = bt(r0), t1 = bt(r1), t2 = bt(r2), t3 = bt(r3);
                    a2h[kt2][hh * 2 + 0] = pk(t0, t1);
                    a2h[kt2][hh * 2 + 1] = pk(t2, t3);
                    a2l[kt2][hh * 2 + 0] = pk(r0 - t0, r1 - t1);
                    a2l[kt2][hh * 2 + 1] = pk(r2 - t2, r3 - t3);
                }
                // reorder: frag = {a0(row,k0-7), a1(row+8,k0-7), a2(row,k8-15), a3(row+8,k8-15)}
                // built as [hh=0]->a0,a1 ; [hh=1]->a2,a3  (matches layout above)
            }

            float d2[2][4];
#pragma unroll
            for (int nt2 = 0; nt2 < 2; nt2++)
#pragma unroll
                for (int u = 0; u < 4; u++) d2[nt2][u] = 0.0f;

#pragma unroll
            for (int nt2 = 0; nt2 < 2; nt2++)
#pragma unroll
            for (int kt2 = 0; kt2 < 2; kt2++) {
                uint2 bh = W2H[(kt2 * 2 + nt2) * 32 + lane];
                uint2 bl = W2L[(kt2 * 2 + nt2) * 32 + lane];
                mma16816(d2[nt2], a2h[kt2], bh.x, bh.y);
                mma16816(d2[nt2], a2h[kt2], bl.x, bl.y);
                mma16816(d2[nt2], a2l[kt2], bh.x, bh.y);
            }

            const int r0w = wid * 32 + smt * 16 + nrow;
#pragma unroll
            for (int nt2 = 0; nt2 < 2; nt2++) {
                const int col = nt2 * 8 + q * 2;
                ZS[r0w * 17 + col]       = d2[nt2][0];
                ZS[r0w * 17 + col + 1]   = d2[nt2][1];
                ZS[(r0w + 8) * 17 + col]     = d2[nt2][2];
                ZS[(r0w + 8) * 17 + col + 1] = d2[nt2][3];
            }
        }
        __syncwarp();

        float z[13];
#pragma unroll
        for (int m = 0; m < 13; m++) z[m] = ZS[tid * 17 + m] + __ldg(&b2[m]);
        epilogue(z, dd, p, out);
        __syncwarp();
    }
}

extern "C" void kernel_launch(void* const* d_in, const int* in_sizes, int n_in,
                              void* d_out, int out_size)
{
    const float* se  = (const float*)d_in[0];
    const float* te  = (const float*)d_in[1];
    const float* sr  = (const float*)d_in[2];
    const float* hc  = (const float*)d_in[3];
    const float* rot = (const float*)d_in[4];
    const float* w1  = (const float*)d_in[5];
    const float* b1  = (const float*)d_in[6];
    const float* w2  = (const float*)d_in[7];
    const float* b2  = (const float*)d_in[8];
    float* out = (float*)d_out;

    energy_cnn_hmma_kernel<<<NCTA, 128>>>(se, te, sr, hc, rot, w1, b1, w2, b2, out);
}